// round 3
// baseline (speedup 1.0000x reference)
#include <cuda_runtime.h>
#include <math.h>
#include <stdint.h>

// ---------------- problem constants ----------------
#define BATCH 32
#define TT    1024
#define FF    40
#define HH    256
#define G4    1024      // 4*H
#define T2    342
#define V1    30        // V+1

// output layout (float32)
#define OFF_CTC_S 0
#define OFF_LEN_S 328320
#define OFF_CTC_C 328352
#define OFF_LEN_C 656672
#define OFF_CLOSE 656704

// ---------------- scratch (device globals; no allocation) ----------------
__device__ float g_xz[2u*32u*1024u*1024u];      // 256 MB: xz for lstm0; reused (smaller) for lstm1
__device__ float g_pool[2*32*342*256];          // pooled lstm0 output
__device__ float g_hA[2*32*342*256];            // lstm1 pass A output
__device__ float g_hB[2*32*342*256];            // lstm1 pass B output
__device__ float g_hbuf[16*2*4*256];            // [gang][parity][b][k]
__device__ int   g_flags[16*8];                 // [gang][colgroup]

// ---------------- sync helpers ----------------
__device__ __forceinline__ int ldg_acquire(const int* p) {
    int v;
    asm volatile("ld.acquire.gpu.global.b32 %0, [%1];" : "=r"(v) : "l"(p) : "memory");
    return v;
}
__device__ __forceinline__ void stg_release(int* p, int v) {
    asm volatile("st.release.gpu.global.b32 [%0], %1;" :: "l"(p), "r"(v) : "memory");
}

__global__ void zero_flags_kernel() {
    if (threadIdx.x < 16*8) g_flags[threadIdx.x] = 0;
}

// ---------------- tiled GEMM with bias: out[M,1024] = A[M,K] @ W[K,1024] + b ----------------
// mode 0: A = x (shared across branches), clip to [-3,3], out = g_xz (stride 32*1024*1024)
// mode 1: A = g_pool (branch slice),                    out = g_xz (stride 32*342*1024)
// mode 2: A = g_hA  (branch slice),                    out = g_xz (stride 32*342*1024)
__global__ __launch_bounds__(256) void gemm_bias_kernel(
    const float* __restrict__ Aext,
    const float* __restrict__ W0, const float* __restrict__ W1,
    const float* __restrict__ b0, const float* __restrict__ b1,
    int M, int K, int mode)
{
    const int branch = blockIdx.z;
    const float* W = branch ? W1 : W0;
    const float* bias = branch ? b1 : b0;

    const float* A;
    float* out;
    if (mode == 0) {
        A = Aext;                                   // x shared
        out = g_xz + (size_t)branch * (32u*1024u*1024u);
    } else if (mode == 1) {
        A = g_pool + (size_t)branch * (32*342*256);
        out = g_xz + (size_t)branch * (32u*342u*1024u);
    } else {
        A = g_hA + (size_t)branch * (32*342*256);
        out = g_xz + (size_t)branch * (32u*342u*1024u);
    }

    __shared__ float As[64][17];     // [m][k] padded
    __shared__ float Bs[16][128];

    const int tid = threadIdx.x;
    const int tr = tid >> 5;         // warp id: rows tr*8..tr*8+7
    const int tc = tid & 31;         // lane: cols tc*4..tc*4+3
    const int m0 = blockIdx.y * 64;
    const int n0 = blockIdx.x * 128;

    float acc[8][4];
    #pragma unroll
    for (int i = 0; i < 8; i++)
        #pragma unroll
        for (int j = 0; j < 4; j++) acc[i][j] = 0.f;

    for (int k0 = 0; k0 < K; k0 += 16) {
        // load A tile (64 x 16)
        #pragma unroll
        for (int i = tid; i < 1024; i += 256) {
            int m = i >> 4, k = i & 15;
            float v = 0.f;
            if (k0 + k < K) {
                v = A[(size_t)(m0 + m) * K + k0 + k];
                if (mode == 0) v = fminf(3.f, fmaxf(-3.f, v));
            }
            As[m][k] = v;
        }
        // load B tile (16 x 128)
        #pragma unroll
        for (int i = tid; i < 2048; i += 256) {
            int k = i >> 7, n = i & 127;
            Bs[k][n] = (k0 + k < K) ? W[(size_t)(k0 + k) * 1024 + n0 + n] : 0.f;
        }
        __syncthreads();
        #pragma unroll
        for (int k = 0; k < 16; k++) {
            float4 bv = *(const float4*)&Bs[k][tc * 4];
            #pragma unroll
            for (int i = 0; i < 8; i++) {
                float a = As[tr * 8 + i][k];
                acc[i][0] += a * bv.x;
                acc[i][1] += a * bv.y;
                acc[i][2] += a * bv.z;
                acc[i][3] += a * bv.w;
            }
        }
        __syncthreads();
    }
    float4 bv = *(const float4*)&bias[n0 + tc * 4];
    #pragma unroll
    for (int i = 0; i < 8; i++) {
        float4 r = make_float4(acc[i][0] + bv.x, acc[i][1] + bv.y,
                               acc[i][2] + bv.z, acc[i][3] + bv.w);
        *(float4*)&out[(size_t)(m0 + tr * 8 + i) * 1024 + n0 + tc * 4] = r;
    }
}

// ---------------- persistent recurrent LSTM kernel ----------------
// grid = 128 blocks: blockIdx.x = gang*8 + cg; gang = branch*8 + bg
// block owns 32 hidden units (j0 = cg*32), all 4 gates (128 columns), all 256 k rows.
// 256 threads: warp kg (0..7) owns k rows kg*32..+31; lane owns local cols lane*4..+3.
// mode 0: lstm0 (T=1024), xz stride 1024 rows/batch, writes g_pool (fused maxpool3-SAME)
// mode 1: lstm1 pass A (T=342), writes g_hA
// mode 2: lstm1 pass B (T=342), writes g_hB
__global__ __launch_bounds__(256, 1) void lstm_rec_kernel(
    const float* __restrict__ Wr0, const float* __restrict__ Wr1,
    const int* __restrict__ x_len, int T, int mode)
{
    const int blk = blockIdx.x;
    const int gang = blk >> 3;
    const int cg = blk & 7;
    const int branch = gang >> 3;
    const int bg = gang & 7;
    const int j0 = cg * 32;
    const float* Wr = branch ? Wr1 : Wr0;

    const int tid = threadIdx.x;
    const int kg = tid >> 5;
    const int lane = tid & 31;
    const int kbase = kg * 32;

    // ---- load weight slice into registers (once) ----
    float4 wreg[32];
    {
        const int c0 = lane * 4;
        const int gate = c0 >> 5;
        const int jj = c0 & 31;
        const float* wb = Wr + gate * 256 + j0 + jj;
        #pragma unroll
        for (int kk = 0; kk < 32; kk++) {
            const float* wr = wb + (size_t)(kbase + kk) * 1024;
            wreg[kk] = make_float4(wr[0], wr[1], wr[2], wr[3]);
        }
    }

    __shared__ float h_s[4][256];
    __shared__ float ps[8][4][128];
    __shared__ float zs[4][128];

    // gate-thread state (tid < 128): b = tid>>5, jj = tid&31
    const int gb = tid >> 5;
    const int gjj = tid & 31;
    float cst = 0.f;
    float poolm = __int_as_float(0xff800000);  // -inf
    int mylen = 0;
    int b_glob = 0;
    if (tid < 128) {
        b_glob = bg * 4 + gb;
        int xl = x_len[b_glob];
        mylen = (mode == 0) ? xl : (xl + 2) / 3;
    }

    const int Tstride = (mode == 0) ? 1024 : 342;
    const float* xz = g_xz + (size_t)branch * 32u * (size_t)Tstride * 1024u;

    float* hbuf = g_hbuf + gang * 2048;      // [parity][b][k]
    int* flags = g_flags + gang * 8;

    // reduce-slot mapping (each thread handles r=tid and r=tid+256)
    const int rb1 = tid >> 7, rc1 = tid & 127;
    const int rb2 = (tid + 256) >> 7, rc2 = (tid + 256) & 127;
    const size_t xcol1 = (size_t)((rc1 >> 5) << 8) + j0 + (rc1 & 31);
    const size_t xcol2 = (size_t)((rc2 >> 5) << 8) + j0 + (rc2 & 31);
    const size_t xrow1 = (size_t)(bg * 4 + rb1) * Tstride;
    const size_t xrow2 = (size_t)(bg * 4 + rb2) * Tstride;

    for (int t = 0; t < T; t++) {
        // ---- acquire h(t) ----
        if (t == 0) {
            ((float4*)h_s)[tid] = make_float4(0.f, 0.f, 0.f, 0.f);
            __syncthreads();
        } else {
            if (tid < 8) {
                while (ldg_acquire(&flags[tid]) < t) __nanosleep(32);
            }
            __syncthreads();
            const float4* src = (const float4*)(hbuf + (size_t)(t & 1) * 1024);
            ((float4*)h_s)[tid] = __ldcg(&src[tid]);   // L2 read (L1 not coherent)
            __syncthreads();
        }

        // ---- prefetch xz for this step ----
        float xz1v = xz[(xrow1 + t) * 1024 + xcol1];
        float xz2v = xz[(xrow2 + t) * 1024 + xcol2];

        // ---- GEMM: partial z over owned k rows ----
        #pragma unroll
        for (int b = 0; b < 4; b++) {
            float ax = 0.f, ay = 0.f, az = 0.f, aw = 0.f;
            #pragma unroll
            for (int kk4 = 0; kk4 < 8; kk4++) {
                float4 h4 = *(const float4*)&h_s[b][kbase + 4 * kk4];
                float4 w;
                w = wreg[4*kk4+0]; ax += h4.x*w.x; ay += h4.x*w.y; az += h4.x*w.z; aw += h4.x*w.w;
                w = wreg[4*kk4+1]; ax += h4.y*w.x; ay += h4.y*w.y; az += h4.y*w.z; aw += h4.y*w.w;
                w = wreg[4*kk4+2]; ax += h4.z*w.x; ay += h4.z*w.y; az += h4.z*w.z; aw += h4.z*w.w;
                w = wreg[4*kk4+3]; ax += h4.w*w.x; ay += h4.w*w.y; az += h4.w*w.z; aw += h4.w*w.w;
            }
            *(float4*)&ps[kg][b][4 * lane] = make_float4(ax, ay, az, aw);
        }
        __syncthreads();

        // ---- reduce across k-groups + add xz ----
        float z1 = xz1v, z2 = xz2v;
        #pragma unroll
        for (int q = 0; q < 8; q++) {
            z1 += ps[q][rb1][rc1];
            z2 += ps[q][rb2][rc2];
        }
        zs[rb1][rc1] = z1;
        zs[rb2][rc2] = z2;
        __syncthreads();

        // ---- gates / state update / publish ----
        if (tid < 128) {
            float zi = zs[gb][gjj];
            float zf = zs[gb][32 + gjj];
            float zg = zs[gb][64 + gjj];
            float zo = zs[gb][96 + gjj];
            float iv = 1.f / (1.f + expf(-zi));
            float fv = 1.f / (1.f + expf(-zf));
            float gv = tanhf(zg);
            float ov = 1.f / (1.f + expf(-zo));
            float cn = fv * cst + iv * gv;
            float hn = ov * tanhf(cn);
            bool m = (t < mylen);
            float hp = h_s[gb][j0 + gjj];
            float hv = m ? hn : hp;
            cst = m ? cn : cst;
            hbuf[(size_t)((t + 1) & 1) * 1024 + gb * 256 + j0 + gjj] = hv;
            if (mode == 0) {
                poolm = fmaxf(poolm, hv);
                if ((t % 3) == 1) {           // window i = t/3 complete
                    int i = t / 3;
                    g_pool[((size_t)(branch * 32 + b_glob) * 342 + i) * 256 + j0 + gjj] = poolm;
                    poolm = __int_as_float(0xff800000);
                }
            } else {
                float* ho = (mode == 1) ? g_hA : g_hB;
                ho[((size_t)(branch * 32 + b_glob) * 342 + t) * 256 + j0 + gjj] = hv;
            }
            __threadfence();
        }
        __syncthreads();
        if (tid == 0) stg_release(&flags[cg], t + 1);
    }

    // flush final pool window (covers t = 1022,1023)
    if (mode == 0 && tid < 128) {
        g_pool[((size_t)(branch * 32 + b_glob) * 342 + 341) * 256 + j0 + gjj] = poolm;
    }
}

// ---------------- CTC projection: out = hB @ ctc_w + ctc_b ----------------
// rows = 2*32*342 = 21888 (flat in g_hB); block handles 8 rows x 30 cols
__global__ __launch_bounds__(256) void ctc_kernel(
    const float* __restrict__ W, const float* __restrict__ bias, float* __restrict__ out)
{
    __shared__ float As[8][256];
    const int r0 = blockIdx.x * 8;
    for (int i = threadIdx.x; i < 2048; i += 256) {
        As[i >> 8][i & 255] = g_hB[(size_t)r0 * 256 + i];
    }
    __syncthreads();
    if (threadIdx.x < 240) {
        const int rl = threadIdx.x / 30;
        const int n = threadIdx.x % 30;
        float acc = bias[n];
        #pragma unroll 8
        for (int k = 0; k < 256; k++) acc += As[rl][k] * __ldg(&W[k * 30 + n]);
        const int r = r0 + rl;
        const int branch = r / 10944;
        const int idx = r - branch * 10944;
        const size_t o = (branch ? (size_t)OFF_CTC_C : (size_t)OFF_CTC_S) + (size_t)idx * 30 + n;
        out[o] = acc;
    }
}

// ---------------- lens + close ----------------
__global__ void finalize_kernel(const int* __restrict__ x_len, float* __restrict__ out)
{
    const int b = blockIdx.x;
    const float* s = out + OFF_CTC_S + (size_t)b * 10260;
    const float* c = out + OFF_CTC_C + (size_t)b * 10260;
    int ok = 1;
    for (int i = threadIdx.x; i < 10260; i += 256) {
        if (!(fabsf(s[i] - c[i]) < 1e-5f)) ok = 0;
    }
    int allok = __syncthreads_and(ok);
    if (threadIdx.x == 0) {
        float len = (float)((x_len[b] + 2) / 3);
        out[OFF_LEN_S + b] = len;
        out[OFF_LEN_C + b] = len;
        out[OFF_CLOSE + b] = allok ? 1.f : 0.f;
    }
}

// ---------------- launch ----------------
extern "C" void kernel_launch(void* const* d_in, const int* in_sizes, int n_in,
                              void* d_out, int out_size)
{
    const float* x      = (const float*)d_in[0];
    const int*   x_len  = (const int*)  d_in[1];
    const float* ws0_k  = (const float*)d_in[2];
    const float* ws0_r  = (const float*)d_in[3];
    const float* ws0_b  = (const float*)d_in[4];
    const float* ws1_k  = (const float*)d_in[5];
    const float* ws1_r  = (const float*)d_in[6];
    const float* ws1_b  = (const float*)d_in[7];
    const float* wc0_k  = (const float*)d_in[8];
    const float* wc0_r  = (const float*)d_in[9];
    const float* wc0_b  = (const float*)d_in[10];
    const float* wc1_k  = (const float*)d_in[11];
    const float* wc1_r  = (const float*)d_in[12];
    const float* wc1_b  = (const float*)d_in[13];
    const float* ctc_w  = (const float*)d_in[14];
    const float* ctc_b  = (const float*)d_in[15];
    float* out = (float*)d_out;

    // xz0 = clip(x) @ Wk0 + b0   (M = 32*1024, K = 40)
    gemm_bias_kernel<<<dim3(8, 512, 2), 256>>>(x, ws0_k, wc0_k, ws0_b, wc0_b, 32768, 40, 0);

    // lstm0 + fused maxpool3
    zero_flags_kernel<<<1, 128>>>();
    lstm_rec_kernel<<<128, 256>>>(ws0_r, wc0_r, x_len, 1024, 0);

    // xz1A = pooled @ Wk1 + b1   (M = 32*342, K = 256)
    gemm_bias_kernel<<<dim3(8, 171, 2), 256>>>(nullptr, ws1_k, wc1_k, ws1_b, wc1_b, 10944, 256, 1);

    // lstm1 pass A
    zero_flags_kernel<<<1, 128>>>();
    lstm_rec_kernel<<<128, 256>>>(ws1_r, wc1_r, x_len, 342, 1);

    // xz1B = hA @ Wk1 + b1
    gemm_bias_kernel<<<dim3(8, 171, 2), 256>>>(nullptr, ws1_k, wc1_k, ws1_b, wc1_b, 10944, 256, 2);

    // lstm1 pass B
    zero_flags_kernel<<<1, 128>>>();
    lstm_rec_kernel<<<128, 256>>>(ws1_r, wc1_r, x_len, 342, 2);

    // CTC projection for both branches
    ctc_kernel<<<2736, 256>>>(ctc_w, ctc_b, out);

    // lens + close
    finalize_kernel<<<32, 256>>>(x_len, out);
}

// round 4
// speedup vs baseline: 1.0774x; 1.0774x over previous
#include <cuda_runtime.h>
#include <math.h>
#include <stdint.h>

typedef unsigned long long ull;

// ---------------- problem constants ----------------
#define BATCH 32
#define TT    1024
#define FF    40
#define HH    256
#define G4    1024      // 4*H
#define T2    342
#define V1    30        // V+1

// output layout (float32)
#define OFF_CTC_S 0
#define OFF_LEN_S 328320
#define OFF_CTC_C 328352
#define OFF_LEN_C 656672
#define OFF_CLOSE 656704

// ---------------- scratch (device globals; no allocation) ----------------
__device__ float g_xz[2u*32u*1024u*1024u];      // 256 MB: xz for lstm0; reused (smaller) for lstm1
__device__ float g_pool[2*32*342*256];          // pooled lstm0 output
__device__ float g_hA[2*32*342*256];            // lstm1 pass A output
__device__ float g_hB[2*32*342*256];            // lstm1 pass B output

// ---------------- f32x2 helpers ----------------
__device__ __forceinline__ ull ffma2(ull a, ull b, ull c) {
    ull d;
    asm("fma.rn.f32x2 %0, %1, %2, %3;" : "=l"(d) : "l"(a), "l"(b), "l"(c));
    return d;
}
__device__ __forceinline__ ull fadd2(ull a, ull b) {
    ull d;
    asm("add.rn.f32x2 %0, %1, %2;" : "=l"(d) : "l"(a), "l"(b));
    return d;
}
__device__ __forceinline__ uint32_t smem_u32(const void* p) {
    uint32_t a;
    asm("{ .reg .u64 t; cvta.to.shared.u64 t, %1; cvt.u32.u64 %0, t; }" : "=r"(a) : "l"(p));
    return a;
}
__device__ __forceinline__ uint32_t mapa_rank(uint32_t addr, uint32_t rank) {
    uint32_t r;
    asm("mapa.shared::cluster.u32 %0, %1, %2;" : "=r"(r) : "r"(addr), "r"(rank));
    return r;
}
__device__ __forceinline__ void mbar_init(uint32_t addr, uint32_t count) {
    asm volatile("mbarrier.init.shared.b64 [%0], %1;" :: "r"(addr), "r"(count) : "memory");
}
__device__ __forceinline__ void mbar_expect(uint32_t addr, uint32_t tx) {
    asm volatile("mbarrier.arrive.expect_tx.shared.b64 _, [%0], %1;" :: "r"(addr), "r"(tx) : "memory");
}
__device__ __forceinline__ void mbar_wait(uint32_t addr, uint32_t parity) {
    asm volatile(
        "{\n\t.reg .pred P;\n"
        "LW_%=:\n\t"
        "mbarrier.try_wait.parity.acquire.cluster.shared::cta.b64 P, [%0], %1, 0x989680;\n\t"
        "@P bra LD_%=;\n\t"
        "bra LW_%=;\n"
        "LD_%=:\n\t}"
        :: "r"(addr), "r"(parity) : "memory");
}
__device__ __forceinline__ void st_async_b64(uint32_t raddr, ull v, uint32_t rmbar) {
    asm volatile("st.async.shared::cluster.mbarrier::complete_tx::bytes.b64 [%0], %1, [%2];"
                 :: "r"(raddr), "l"(v), "r"(rmbar) : "memory");
}

// ---------------- tiled GEMM with bias: out[M,1024] = A[M,K] @ W[K,1024] + b ----------------
__global__ __launch_bounds__(256) void gemm_bias_kernel(
    const float* __restrict__ Aext,
    const float* __restrict__ W0, const float* __restrict__ W1,
    const float* __restrict__ b0, const float* __restrict__ b1,
    int M, int K, int mode)
{
    const int branch = blockIdx.z;
    const float* W = branch ? W1 : W0;
    const float* bias = branch ? b1 : b0;

    const float* A;
    float* out;
    if (mode == 0) {
        A = Aext;
        out = g_xz + (size_t)branch * (32u*1024u*1024u);
    } else if (mode == 1) {
        A = g_pool + (size_t)branch * (32*342*256);
        out = g_xz + (size_t)branch * (32u*342u*1024u);
    } else {
        A = g_hA + (size_t)branch * (32*342*256);
        out = g_xz + (size_t)branch * (32u*342u*1024u);
    }

    __shared__ float As[64][17];
    __shared__ float Bs[16][128];

    const int tid = threadIdx.x;
    const int tr = tid >> 5;
    const int tc = tid & 31;
    const int m0 = blockIdx.y * 64;
    const int n0 = blockIdx.x * 128;

    float acc[8][4];
    #pragma unroll
    for (int i = 0; i < 8; i++)
        #pragma unroll
        for (int j = 0; j < 4; j++) acc[i][j] = 0.f;

    for (int k0 = 0; k0 < K; k0 += 16) {
        #pragma unroll
        for (int i = tid; i < 1024; i += 256) {
            int m = i >> 4, k = i & 15;
            float v = 0.f;
            if (k0 + k < K) {
                v = A[(size_t)(m0 + m) * K + k0 + k];
                if (mode == 0) v = fminf(3.f, fmaxf(-3.f, v));
            }
            As[m][k] = v;
        }
        #pragma unroll
        for (int i = tid; i < 2048; i += 256) {
            int k = i >> 7, n = i & 127;
            Bs[k][n] = (k0 + k < K) ? W[(size_t)(k0 + k) * 1024 + n0 + n] : 0.f;
        }
        __syncthreads();
        #pragma unroll
        for (int k = 0; k < 16; k++) {
            float4 bv = *(const float4*)&Bs[k][tc * 4];
            #pragma unroll
            for (int i = 0; i < 8; i++) {
                float a = As[tr * 8 + i][k];
                acc[i][0] += a * bv.x;
                acc[i][1] += a * bv.y;
                acc[i][2] += a * bv.z;
                acc[i][3] += a * bv.w;
            }
        }
        __syncthreads();
    }
    float4 bv = *(const float4*)&bias[n0 + tc * 4];
    #pragma unroll
    for (int i = 0; i < 8; i++) {
        float4 r = make_float4(acc[i][0] + bv.x, acc[i][1] + bv.y,
                               acc[i][2] + bv.z, acc[i][3] + bv.w);
        *(float4*)&out[(size_t)(m0 + tr * 8 + i) * 1024 + n0 + tc * 4] = r;
    }
}

// ---------------- persistent recurrent LSTM kernel (8-CTA cluster gangs) ----------------
// grid = 128 blocks: blockIdx.x = gang*8 + cg; gang = branch*8 + bg; cg = cluster rank.
// Block owns 32 hidden units (j0 = cg*32), all 4 gates (128 local cols), all 256 k rows.
// 256 threads: kg = tid>>6 owns k rows kg*64..+63; cp = tid&63 owns local cols 2cp,2cp+1.
// h exchanged through cluster DSMEM with st.async + 2 mbarriers (step parity).
__global__ void __launch_bounds__(256, 1) __cluster_dims__(8, 1, 1)
lstm_rec_kernel(
    const float* __restrict__ Wr0, const float* __restrict__ Wr1,
    const int* __restrict__ x_len, int T, int mode)
{
    const int blk = blockIdx.x;
    const int gang = blk >> 3;
    const int cg = blk & 7;
    const int branch = gang >> 3;
    const int bg = gang & 7;
    const int j0 = cg * 32;
    const float* Wr = branch ? Wr1 : Wr0;

    const int tid = threadIdx.x;
    const int kg = tid >> 6;          // k-group 0..3
    const int cp = tid & 63;          // column pair 0..63
    const int kbase = kg * 64;

    __shared__ __align__(16) ull h2_s[2][4][256];   // duplicated h, double buffered (16KB)
    __shared__ __align__(16) ull ps[4][4][64];      // partial sums (8KB)
    __shared__ __align__(16) float zs[4][128];      // reduced z (2KB)
    __shared__ __align__(8) ull mbar_s[2];

    // ---- mbarrier init + initial expects ----
    const uint32_t mb0 = smem_u32(&mbar_s[0]);
    const uint32_t mb1 = smem_u32(&mbar_s[1]);
    if (tid == 0) {
        mbar_init(mb0, 1);
        mbar_init(mb1, 1);
    }
    __syncthreads();
    if (tid == 0) {
        mbar_expect(mb0, 8192);   // phase 0 of mbar0: h(2)
        mbar_expect(mb1, 8192);   // phase 0 of mbar1: h(1)
    }

    // ---- zero h(0) buffer ----
    {
        ull* p = &h2_s[0][0][0];
        #pragma unroll
        for (int i = tid; i < 1024; i += 256) p[i] = 0ull;
    }

    // ---- load packed weight slice into registers ----
    ull wpack[64];
    {
        const int gate = cp >> 4;                 // (2cp)/32
        const int jj2 = (2 * cp) & 31;
        const float* wb = Wr + (size_t)kbase * 1024 + gate * 256 + j0 + jj2;
        #pragma unroll
        for (int kk = 0; kk < 64; kk++)
            wpack[kk] = *(const ull*)(wb + (size_t)kk * 1024);
    }

    // ---- per-role constants ----
    // gate role (tid < 128): gb = tid>>5, gjj = tid&31
    const int gb = tid >> 5;
    const int gjj = tid & 31;
    float cst = 0.f;
    float poolm = __int_as_float(0xff800000);
    int mylen = 0, b_glob = 0;
    if (tid < 128) {
        b_glob = bg * 4 + gb;
        int xl = x_len[b_glob];
        mylen = (mode == 0) ? xl : (xl + 2) / 3;
    }
    // peer base addresses for st.async (8 ranks)
    uint32_t peer_h2[8], peer_mb[8];
    {
        uint32_t h2b = smem_u32(&h2_s[0][0][0]);
        #pragma unroll
        for (int r = 0; r < 8; r++) {
            peer_h2[r] = mapa_rank(h2b, r);
            peer_mb[r] = mapa_rank(mb0, r);
        }
    }

    // reduce role: rb = tid>>6, rcp = tid&63 -> local cols 2rcp,2rcp+1
    const int rb = tid >> 6;
    const int rcp = tid & 63;
    const int Tstride = (mode == 0) ? 1024 : 342;
    const int rgate = rcp >> 4;
    const int rjj2 = (2 * rcp) & 31;
    const float* xzp = g_xz + (size_t)branch * 32u * (size_t)Tstride * 1024u
                     + (size_t)(bg * 4 + rb) * Tstride * 1024u
                     + rgate * 256 + j0 + rjj2;

    float* poolp = g_pool + ((size_t)(branch * 32 + b_glob) * 342) * 256 + j0 + gjj;
    float* hop = ((mode == 1) ? g_hA : g_hB) + ((size_t)(branch * 32 + b_glob) * 342) * 256 + j0 + gjj;

    __syncthreads();
    // cluster sync: mbarriers + expects visible before any peer st.async
    asm volatile("barrier.cluster.arrive.aligned;" ::: "memory");
    asm volatile("barrier.cluster.wait.aligned;" ::: "memory");

    uint32_t phase[2] = {0, 0};

    for (int t = 0; t < T; t++) {
        const int par = t & 1;
        const int par1 = par ^ 1;

        // prefetch xz (independent of h)
        ull xzbits = *(const ull*)xzp;
        xzp += 1024;

        // ---- wait for h(t) ----
        if (t > 0) {
            uint32_t mb = par ? mb1 : mb0;
            mbar_wait(mb, phase[par]);
            phase[par] ^= 1;
            if (tid == 0) mbar_expect(mb, 8192);   // next phase of this barrier: h(t+2)
        }

        // ---- GEMM partials: acc[b] over owned 64 k, 1 column pair ----
        ull a0 = 0, a1 = 0, a2 = 0, a3 = 0;
        #pragma unroll
        for (int kk = 0; kk < 64; kk += 2) {
            ulonglong2 h0 = *(const ulonglong2*)&h2_s[par][0][kbase + kk];
            ulonglong2 h1 = *(const ulonglong2*)&h2_s[par][1][kbase + kk];
            ulonglong2 h2 = *(const ulonglong2*)&h2_s[par][2][kbase + kk];
            ulonglong2 h3 = *(const ulonglong2*)&h2_s[par][3][kbase + kk];
            ull w0 = wpack[kk], w1 = wpack[kk + 1];
            a0 = ffma2(h0.x, w0, a0); a0 = ffma2(h0.y, w1, a0);
            a1 = ffma2(h1.x, w0, a1); a1 = ffma2(h1.y, w1, a1);
            a2 = ffma2(h2.x, w0, a2); a2 = ffma2(h2.y, w1, a2);
            a3 = ffma2(h3.x, w0, a3); a3 = ffma2(h3.y, w1, a3);
        }
        ps[kg][0][cp] = a0;
        ps[kg][1][cp] = a1;
        ps[kg][2][cp] = a2;
        ps[kg][3][cp] = a3;
        __syncthreads();

        // ---- reduce 4 k-groups + xz ----
        {
            ull z = xzbits;
            z = fadd2(z, ps[0][rb][rcp]);
            z = fadd2(z, ps[1][rb][rcp]);
            z = fadd2(z, ps[2][rb][rcp]);
            z = fadd2(z, ps[3][rb][rcp]);
            *(ull*)&zs[rb][2 * rcp] = z;
        }
        __syncthreads();

        // ---- gates / state / publish via DSMEM ----
        if (tid < 128) {
            float zi = zs[gb][gjj];
            float zf = zs[gb][32 + gjj];
            float zg = zs[gb][64 + gjj];
            float zo = zs[gb][96 + gjj];
            float iv = 1.f / (1.f + expf(-zi));
            float fv = 1.f / (1.f + expf(-zf));
            float gv = tanhf(zg);
            float ov = 1.f / (1.f + expf(-zo));
            float cn = fv * cst + iv * gv;
            float hn = ov * tanhf(cn);
            bool m = (t < mylen);
            float hp = ((const float*)&h2_s[par][gb][j0 + gjj])[0];
            float hv = m ? hn : hp;
            cst = m ? cn : cst;

            // outputs
            if (mode == 0) {
                poolm = fmaxf(poolm, hv);
                if ((t % 3) == 1) {
                    poolp[(size_t)(t / 3) * 256] = poolm;
                    poolm = __int_as_float(0xff800000);
                }
            } else {
                hop[(size_t)t * 256] = hv;
            }

            // send duplicated h(t+1) to all 8 cluster CTAs
            if (t + 1 < T) {
                ull hd;
                asm("mov.b64 %0, {%1, %2};" : "=l"(hd) : "f"(hv), "f"(hv));
                const uint32_t hoff = (uint32_t)(((par1 * 4 + gb) * 256 + (j0 + gjj)) * 8);
                const uint32_t moff = (uint32_t)(par1 * 8);   // mbar_s[par1]
                #pragma unroll
                for (int r = 0; r < 8; r++)
                    st_async_b64(peer_h2[r] + hoff, hd, peer_mb[r] + moff);
            }
        }
    }

    // flush final pool window (covers t = 1022,1023)
    if (mode == 0 && tid < 128) {
        poolp[341u * 256] = poolm;
    }
}

// ---------------- CTC projection: out = hB @ ctc_w + ctc_b ----------------
__global__ __launch_bounds__(256) void ctc_kernel(
    const float* __restrict__ W, const float* __restrict__ bias, float* __restrict__ out)
{
    __shared__ float As[8][256];
    const int r0 = blockIdx.x * 8;
    for (int i = threadIdx.x; i < 2048; i += 256) {
        As[i >> 8][i & 255] = g_hB[(size_t)r0 * 256 + i];
    }
    __syncthreads();
    if (threadIdx.x < 240) {
        const int rl = threadIdx.x / 30;
        const int n = threadIdx.x % 30;
        float acc = bias[n];
        #pragma unroll 8
        for (int k = 0; k < 256; k++) acc += As[rl][k] * __ldg(&W[k * 30 + n]);
        const int r = r0 + rl;
        const int branch = r / 10944;
        const int idx = r - branch * 10944;
        const size_t o = (branch ? (size_t)OFF_CTC_C : (size_t)OFF_CTC_S) + (size_t)idx * 30 + n;
        out[o] = acc;
    }
}

// ---------------- lens + close ----------------
__global__ void finalize_kernel(const int* __restrict__ x_len, float* __restrict__ out)
{
    const int b = blockIdx.x;
    const float* s = out + OFF_CTC_S + (size_t)b * 10260;
    const float* c = out + OFF_CTC_C + (size_t)b * 10260;
    int ok = 1;
    for (int i = threadIdx.x; i < 10260; i += 256) {
        if (!(fabsf(s[i] - c[i]) < 1e-5f)) ok = 0;
    }
    int allok = __syncthreads_and(ok);
    if (threadIdx.x == 0) {
        float len = (float)((x_len[b] + 2) / 3);
        out[OFF_LEN_S + b] = len;
        out[OFF_LEN_C + b] = len;
        out[OFF_CLOSE + b] = allok ? 1.f : 0.f;
    }
}

// ---------------- launch ----------------
extern "C" void kernel_launch(void* const* d_in, const int* in_sizes, int n_in,
                              void* d_out, int out_size)
{
    const float* x      = (const float*)d_in[0];
    const int*   x_len  = (const int*)  d_in[1];
    const float* ws0_k  = (const float*)d_in[2];
    const float* ws0_r  = (const float*)d_in[3];
    const float* ws0_b  = (const float*)d_in[4];
    const float* ws1_k  = (const float*)d_in[5];
    const float* ws1_r  = (const float*)d_in[6];
    const float* ws1_b  = (const float*)d_in[7];
    const float* wc0_k  = (const float*)d_in[8];
    const float* wc0_r  = (const float*)d_in[9];
    const float* wc0_b  = (const float*)d_in[10];
    const float* wc1_k  = (const float*)d_in[11];
    const float* wc1_r  = (const float*)d_in[12];
    const float* wc1_b  = (const float*)d_in[13];
    const float* ctc_w  = (const float*)d_in[14];
    const float* ctc_b  = (const float*)d_in[15];
    float* out = (float*)d_out;

    // xz0 = clip(x) @ Wk0 + b0   (M = 32*1024, K = 40)
    gemm_bias_kernel<<<dim3(8, 512, 2), 256>>>(x, ws0_k, wc0_k, ws0_b, wc0_b, 32768, 40, 0);

    // lstm0 + fused maxpool3
    lstm_rec_kernel<<<128, 256>>>(ws0_r, wc0_r, x_len, 1024, 0);

    // xz1A = pooled @ Wk1 + b1   (M = 32*342, K = 256)
    gemm_bias_kernel<<<dim3(8, 171, 2), 256>>>(nullptr, ws1_k, wc1_k, ws1_b, wc1_b, 10944, 256, 1);

    // lstm1 pass A
    lstm_rec_kernel<<<128, 256>>>(ws1_r, wc1_r, x_len, 342, 1);

    // xz1B = hA @ Wk1 + b1
    gemm_bias_kernel<<<dim3(8, 171, 2), 256>>>(nullptr, ws1_k, wc1_k, ws1_b, wc1_b, 10944, 256, 2);

    // lstm1 pass B
    lstm_rec_kernel<<<128, 256>>>(ws1_r, wc1_r, x_len, 342, 2);

    // CTC projection for both branches
    ctc_kernel<<<2736, 256>>>(ctc_w, ctc_b, out);

    // lens + close
    finalize_kernel<<<32, 256>>>(x_len, out);
}

// round 5
// speedup vs baseline: 1.4612x; 1.3562x over previous
#include <cuda_runtime.h>
#include <math.h>
#include <stdint.h>

typedef unsigned long long ull;

// ---------------- problem constants ----------------
#define BATCH 32
#define TT    1024
#define FF    40
#define HH    256
#define G4    1024      // 4*H
#define T2    342
#define V1    30        // V+1

// output layout (float32)
#define OFF_CTC_S 0
#define OFF_LEN_S 328320
#define OFF_CTC_C 328352
#define OFF_LEN_C 656672
#define OFF_CLOSE 656704

// ---------------- scratch (device globals; no allocation) ----------------
__device__ float g_xz[2u*32u*1024u*1024u];      // 256 MB: xz for lstm0; reused (smaller) for lstm1
__device__ float g_pool[2*32*342*256];          // pooled lstm0 output
__device__ float g_hA[2*32*342*256];            // lstm1 pass A output
__device__ float g_hB[2*32*342*256];            // lstm1 pass B output

// ---------------- cluster / mbarrier helpers ----------------
__device__ __forceinline__ uint32_t smem_u32(const void* p) {
    uint32_t a;
    asm("{ .reg .u64 t; cvta.to.shared.u64 t, %1; cvt.u32.u64 %0, t; }" : "=r"(a) : "l"(p));
    return a;
}
__device__ __forceinline__ uint32_t mapa_rank(uint32_t addr, uint32_t rank) {
    uint32_t r;
    asm("mapa.shared::cluster.u32 %0, %1, %2;" : "=r"(r) : "r"(addr), "r"(rank));
    return r;
}
__device__ __forceinline__ void mbar_init(uint32_t addr, uint32_t count) {
    asm volatile("mbarrier.init.shared.b64 [%0], %1;" :: "r"(addr), "r"(count) : "memory");
}
__device__ __forceinline__ void mbar_expect(uint32_t addr, uint32_t tx) {
    asm volatile("mbarrier.arrive.expect_tx.shared.b64 _, [%0], %1;" :: "r"(addr), "r"(tx) : "memory");
}
__device__ __forceinline__ void mbar_wait(uint32_t addr, uint32_t parity) {
    asm volatile(
        "{\n\t.reg .pred P;\n"
        "LW_%=:\n\t"
        "mbarrier.try_wait.parity.acquire.cluster.shared::cta.b64 P, [%0], %1, 0x989680;\n\t"
        "@P bra LD_%=;\n\t"
        "bra LW_%=;\n"
        "LD_%=:\n\t}"
        :: "r"(addr), "r"(parity) : "memory");
}
__device__ __forceinline__ void st_async_b32(uint32_t raddr, float v, uint32_t rmbar) {
    asm volatile("st.async.shared::cluster.mbarrier::complete_tx::bytes.b32 [%0], %1, [%2];"
                 :: "r"(raddr), "f"(v), "r"(rmbar) : "memory");
}

// fast sigmoid / tanh (EX2 + RCP based; ~1e-6 rel err)
__device__ __forceinline__ float fsigm(float x) {
    return __fdividef(1.f, 1.f + __expf(-x));
}
__device__ __forceinline__ float ftanh_(float x) {
    return __fdividef(2.f, 1.f + __expf(-2.f * x)) - 1.f;
}

// ---------------- tiled GEMM with bias: out[M,1024] = A[M,K] @ W[K,1024] + b ----------------
__global__ __launch_bounds__(256) void gemm_bias_kernel(
    const float* __restrict__ Aext,
    const float* __restrict__ W0, const float* __restrict__ W1,
    const float* __restrict__ b0, const float* __restrict__ b1,
    int M, int K, int mode)
{
    const int branch = blockIdx.z;
    const float* W = branch ? W1 : W0;
    const float* bias = branch ? b1 : b0;

    const float* A;
    float* out;
    if (mode == 0) {
        A = Aext;
        out = g_xz + (size_t)branch * (32u*1024u*1024u);
    } else if (mode == 1) {
        A = g_pool + (size_t)branch * (32*342*256);
        out = g_xz + (size_t)branch * (32u*342u*1024u);
    } else {
        A = g_hA + (size_t)branch * (32*342*256);
        out = g_xz + (size_t)branch * (32u*342u*1024u);
    }

    __shared__ float As[64][17];
    __shared__ float Bs[16][128];

    const int tid = threadIdx.x;
    const int tr = tid >> 5;
    const int tc = tid & 31;
    const int m0 = blockIdx.y * 64;
    const int n0 = blockIdx.x * 128;

    float acc[8][4];
    #pragma unroll
    for (int i = 0; i < 8; i++)
        #pragma unroll
        for (int j = 0; j < 4; j++) acc[i][j] = 0.f;

    for (int k0 = 0; k0 < K; k0 += 16) {
        #pragma unroll
        for (int i = tid; i < 1024; i += 256) {
            int m = i >> 4, k = i & 15;
            float v = 0.f;
            if (k0 + k < K) {
                v = A[(size_t)(m0 + m) * K + k0 + k];
                if (mode == 0) v = fminf(3.f, fmaxf(-3.f, v));
            }
            As[m][k] = v;
        }
        #pragma unroll
        for (int i = tid; i < 2048; i += 256) {
            int k = i >> 7, n = i & 127;
            Bs[k][n] = (k0 + k < K) ? W[(size_t)(k0 + k) * 1024 + n0 + n] : 0.f;
        }
        __syncthreads();
        #pragma unroll
        for (int k = 0; k < 16; k++) {
            float4 bv = *(const float4*)&Bs[k][tc * 4];
            #pragma unroll
            for (int i = 0; i < 8; i++) {
                float a = As[tr * 8 + i][k];
                acc[i][0] += a * bv.x;
                acc[i][1] += a * bv.y;
                acc[i][2] += a * bv.z;
                acc[i][3] += a * bv.w;
            }
        }
        __syncthreads();
    }
    float4 bv = *(const float4*)&bias[n0 + tc * 4];
    #pragma unroll
    for (int i = 0; i < 8; i++) {
        float4 r = make_float4(acc[i][0] + bv.x, acc[i][1] + bv.y,
                               acc[i][2] + bv.z, acc[i][3] + bv.w);
        *(float4*)&out[(size_t)(m0 + tr * 8 + i) * 1024 + n0 + tc * 4] = r;
    }
}

// ---------------- persistent recurrent LSTM kernel (8-CTA cluster gangs) ----------------
// grid = 128 blocks: blockIdx.x = gang*8 + cg; gang = branch*8 + bg; cg = cluster rank.
// Block owns 32 hidden units (j0 = cg*32), all 4 gates (128 local cols), all 256 k rows.
// 256 threads: warp kg (0..7) owns k rows kg*32..+31; lane owns local cols lane*4..+3.
// h exchanged through cluster DSMEM with st.async.b32 + 2 mbarriers (step parity).
__global__ void __launch_bounds__(256, 1) __cluster_dims__(8, 1, 1)
lstm_rec_kernel(
    const float* __restrict__ Wr0, const float* __restrict__ Wr1,
    const int* __restrict__ x_len, int T, int mode)
{
    const int blk = blockIdx.x;
    const int gang = blk >> 3;
    const int cg = blk & 7;
    const int branch = gang >> 3;
    const int bg = gang & 7;
    const int j0 = cg * 32;
    const float* Wr = branch ? Wr1 : Wr0;

    const int tid = threadIdx.x;
    const int kg = tid >> 5;          // warp = k-group 0..7
    const int lane = tid & 31;
    const int kbase = kg * 32;

    __shared__ float h_s[2][4][256];    // double-buffered h (8KB)
    __shared__ float ps[8][4][128];     // partial sums (16KB)
    __shared__ float zs[4][128];        // reduced z (2KB)
    __shared__ __align__(8) ull mbar_s[2];

    // ---- mbarrier init + initial expects ----
    const uint32_t mb0 = smem_u32(&mbar_s[0]);
    const uint32_t mb1 = smem_u32(&mbar_s[1]);
    if (tid == 0) {
        mbar_init(mb0, 1);
        mbar_init(mb1, 1);
    }
    __syncthreads();
    if (tid == 0) {
        mbar_expect(mb0, 4096);   // phase 0 of mbar0: h(2)
        mbar_expect(mb1, 4096);   // phase 0 of mbar1: h(1)
    }

    // ---- zero h(0) buffer ----
    {
        float* p = &h_s[0][0][0];
        #pragma unroll
        for (int i = tid; i < 1024; i += 256) p[i] = 0.f;
    }

    // ---- load weight slice into registers (once): 32 k x 4 cols ----
    float4 wreg[32];
    {
        const int c0 = lane * 4;
        const int gate = c0 >> 5;
        const int jj = c0 & 31;
        const float* wb = Wr + gate * 256 + j0 + jj;
        #pragma unroll
        for (int kk = 0; kk < 32; kk++) {
            const float* wr = wb + (size_t)(kbase + kk) * 1024;
            wreg[kk] = make_float4(wr[0], wr[1], wr[2], wr[3]);
        }
    }

    // ---- gate role (tid < 128): gb = tid>>5, gjj = tid&31 ----
    const int gb = tid >> 5;
    const int gjj = tid & 31;
    float cst = 0.f;
    float poolm = __int_as_float(0xff800000);
    int mylen = 0, b_glob = 0;
    if (tid < 128) {
        b_glob = bg * 4 + gb;
        int xl = x_len[b_glob];
        mylen = (mode == 0) ? xl : (xl + 2) / 3;
    }

    // peer base addresses for st.async (8 ranks)
    uint32_t peer_h[8], peer_mb[8];
    {
        uint32_t hb = smem_u32(&h_s[0][0][0]);
        #pragma unroll
        for (int r = 0; r < 8; r++) {
            peer_h[r] = mapa_rank(hb, r);
            peer_mb[r] = mapa_rank(mb0, r);
        }
    }

    // reduce role: 2 slots per thread over 512 = 4b x 128c
    const int rb1 = tid >> 7, rc1 = tid & 127;
    const int rb2 = (tid + 256) >> 7, rc2 = (tid + 256) & 127;
    const int Tstride = (mode == 0) ? 1024 : 342;
    const size_t xcol1 = (size_t)((rc1 >> 5) << 8) + j0 + (rc1 & 31);
    const size_t xcol2 = (size_t)((rc2 >> 5) << 8) + j0 + (rc2 & 31);
    const float* xz = g_xz + (size_t)branch * 32u * (size_t)Tstride * 1024u;
    const float* xzp1 = xz + (size_t)(bg * 4 + rb1) * Tstride * 1024u + xcol1;
    const float* xzp2 = xz + (size_t)(bg * 4 + rb2) * Tstride * 1024u + xcol2;

    float* poolp = g_pool + ((size_t)(branch * 32 + b_glob) * 342) * 256 + j0 + gjj;
    float* hop = ((mode == 1) ? g_hA : g_hB) + ((size_t)(branch * 32 + b_glob) * 342) * 256 + j0 + gjj;

    __syncthreads();
    // cluster sync: mbarriers + expects visible before any peer st.async
    asm volatile("barrier.cluster.arrive.aligned;" ::: "memory");
    asm volatile("barrier.cluster.wait.aligned;" ::: "memory");

    uint32_t phase0 = 0, phase1 = 0;

    for (int t = 0; t < T; t++) {
        const int par = t & 1;
        const int par1 = par ^ 1;

        // prefetch xz for this step (independent of h)
        float xz1v = xzp1[(size_t)t * 1024];
        float xz2v = xzp2[(size_t)t * 1024];

        // ---- wait for h(t), re-arm for h(t+2) ----
        if (t > 0) {
            if (par) {
                mbar_wait(mb1, phase1);
                phase1 ^= 1;
                if (tid == 0) mbar_expect(mb1, 4096);
            } else {
                mbar_wait(mb0, phase0);
                phase0 ^= 1;
                if (tid == 0) mbar_expect(mb0, 4096);
            }
        }

        // ---- GEMM: partial z over owned 32 k rows, 4 cols, 4 batches ----
        #pragma unroll
        for (int b = 0; b < 4; b++) {
            float ax = 0.f, ay = 0.f, az = 0.f, aw = 0.f;
            #pragma unroll
            for (int kk4 = 0; kk4 < 8; kk4++) {
                float4 h4 = *(const float4*)&h_s[par][b][kbase + 4 * kk4];
                float4 w;
                w = wreg[4*kk4+0]; ax += h4.x*w.x; ay += h4.x*w.y; az += h4.x*w.z; aw += h4.x*w.w;
                w = wreg[4*kk4+1]; ax += h4.y*w.x; ay += h4.y*w.y; az += h4.y*w.z; aw += h4.y*w.w;
                w = wreg[4*kk4+2]; ax += h4.z*w.x; ay += h4.z*w.y; az += h4.z*w.z; aw += h4.z*w.w;
                w = wreg[4*kk4+3]; ax += h4.w*w.x; ay += h4.w*w.y; az += h4.w*w.z; aw += h4.w*w.w;
            }
            *(float4*)&ps[kg][b][4 * lane] = make_float4(ax, ay, az, aw);
        }
        __syncthreads();

        // ---- reduce across 8 k-groups + add xz ----
        float z1 = xz1v, z2 = xz2v;
        #pragma unroll
        for (int q = 0; q < 8; q++) {
            z1 += ps[q][rb1][rc1];
            z2 += ps[q][rb2][rc2];
        }
        zs[rb1][rc1] = z1;
        zs[rb2][rc2] = z2;
        __syncthreads();

        // ---- gates / state / publish via DSMEM ----
        if (tid < 128) {
            float zi = zs[gb][gjj];
            float zf = zs[gb][32 + gjj];
            float zg = zs[gb][64 + gjj];
            float zo = zs[gb][96 + gjj];
            float iv = fsigm(zi);
            float fv = fsigm(zf);
            float gv = ftanh_(zg);
            float ov = fsigm(zo);
            float cn = fv * cst + iv * gv;
            float hn = ov * ftanh_(cn);
            bool m = (t < mylen);
            float hp = h_s[par][gb][j0 + gjj];
            float hv = m ? hn : hp;
            cst = m ? cn : cst;

            // outputs
            if (mode == 0) {
                poolm = fmaxf(poolm, hv);
                if ((t % 3) == 1) {
                    poolp[(size_t)(t / 3) * 256] = poolm;
                    poolm = __int_as_float(0xff800000);
                }
            } else {
                hop[(size_t)t * 256] = hv;
            }

            // send h(t+1) to all 8 cluster CTAs (4B each)
            if (t + 1 < T) {
                const uint32_t hoff = (uint32_t)((par1 * 1024 + gb * 256 + (j0 + gjj)) * 4);
                const uint32_t moff = (uint32_t)(par1 * 8);   // mbar_s[par1]
                #pragma unroll
                for (int r = 0; r < 8; r++)
                    st_async_b32(peer_h[r] + hoff, hv, peer_mb[r] + moff);
            }
        }
    }

    // flush final pool window (covers t = 1022,1023)
    if (mode == 0 && tid < 128) {
        poolp[341u * 256] = poolm;
    }
}

// ---------------- CTC projection: out = hB @ ctc_w + ctc_b ----------------
__global__ __launch_bounds__(256) void ctc_kernel(
    const float* __restrict__ W, const float* __restrict__ bias, float* __restrict__ out)
{
    __shared__ float As[8][256];
    const int r0 = blockIdx.x * 8;
    for (int i = threadIdx.x; i < 2048; i += 256) {
        As[i >> 8][i & 255] = g_hB[(size_t)r0 * 256 + i];
    }
    __syncthreads();
    if (threadIdx.x < 240) {
        const int rl = threadIdx.x / 30;
        const int n = threadIdx.x % 30;
        float acc = bias[n];
        #pragma unroll 8
        for (int k = 0; k < 256; k++) acc += As[rl][k] * __ldg(&W[k * 30 + n]);
        const int r = r0 + rl;
        const int branch = r / 10944;
        const int idx = r - branch * 10944;
        const size_t o = (branch ? (size_t)OFF_CTC_C : (size_t)OFF_CTC_S) + (size_t)idx * 30 + n;
        out[o] = acc;
    }
}

// ---------------- lens + close ----------------
__global__ void finalize_kernel(const int* __restrict__ x_len, float* __restrict__ out)
{
    const int b = blockIdx.x;
    const float* s = out + OFF_CTC_S + (size_t)b * 10260;
    const float* c = out + OFF_CTC_C + (size_t)b * 10260;
    int ok = 1;
    for (int i = threadIdx.x; i < 10260; i += 256) {
        if (!(fabsf(s[i] - c[i]) < 1e-5f)) ok = 0;
    }
    int allok = __syncthreads_and(ok);
    if (threadIdx.x == 0) {
        float len = (float)((x_len[b] + 2) / 3);
        out[OFF_LEN_S + b] = len;
        out[OFF_LEN_C + b] = len;
        out[OFF_CLOSE + b] = allok ? 1.f : 0.f;
    }
}

// ---------------- launch ----------------
extern "C" void kernel_launch(void* const* d_in, const int* in_sizes, int n_in,
                              void* d_out, int out_size)
{
    const float* x      = (const float*)d_in[0];
    const int*   x_len  = (const int*)  d_in[1];
    const float* ws0_k  = (const float*)d_in[2];
    const float* ws0_r  = (const float*)d_in[3];
    const float* ws0_b  = (const float*)d_in[4];
    const float* ws1_k  = (const float*)d_in[5];
    const float* ws1_r  = (const float*)d_in[6];
    const float* ws1_b  = (const float*)d_in[7];
    const float* wc0_k  = (const float*)d_in[8];
    const float* wc0_r  = (const float*)d_in[9];
    const float* wc0_b  = (const float*)d_in[10];
    const float* wc1_k  = (const float*)d_in[11];
    const float* wc1_r  = (const float*)d_in[12];
    const float* wc1_b  = (const float*)d_in[13];
    const float* ctc_w  = (const float*)d_in[14];
    const float* ctc_b  = (const float*)d_in[15];
    float* out = (float*)d_out;

    // xz0 = clip(x) @ Wk0 + b0   (M = 32*1024, K = 40)
    gemm_bias_kernel<<<dim3(8, 512, 2), 256>>>(x, ws0_k, wc0_k, ws0_b, wc0_b, 32768, 40, 0);

    // lstm0 + fused maxpool3
    lstm_rec_kernel<<<128, 256>>>(ws0_r, wc0_r, x_len, 1024, 0);

    // xz1A = pooled @ Wk1 + b1   (M = 32*342, K = 256)
    gemm_bias_kernel<<<dim3(8, 171, 2), 256>>>(nullptr, ws1_k, wc1_k, ws1_b, wc1_b, 10944, 256, 1);

    // lstm1 pass A
    lstm_rec_kernel<<<128, 256>>>(ws1_r, wc1_r, x_len, 342, 1);

    // xz1B = hA @ Wk1 + b1
    gemm_bias_kernel<<<dim3(8, 171, 2), 256>>>(nullptr, ws1_k, wc1_k, ws1_b, wc1_b, 10944, 256, 2);

    // lstm1 pass B
    lstm_rec_kernel<<<128, 256>>>(ws1_r, wc1_r, x_len, 342, 2);

    // CTC projection for both branches
    ctc_kernel<<<2736, 256>>>(ctc_w, ctc_b, out);

    // lens + close
    finalize_kernel<<<32, 256>>>(x_len, out);
}